// round 14
// baseline (speedup 1.0000x reference)
#include <cuda_runtime.h>
#include <cuda_fp16.h>
#include <cstdint>

#define BATCH 4
#define HH 256
#define WW 256
#define NCC 64
#define NHID 18
#define EPSV 1e-5f

typedef __half fp16;

// ---------------- device scratch ----------------
__device__ __align__(16) fp16 g_h0[BATCH * HH * WW * NCC];
__device__ __align__(16) fp16 g_l0[BATCH * HH * WW * NCC];
__device__ __align__(16) fp16 g_h1[BATCH * HH * WW * NCC];
__device__ __align__(16) fp16 g_l1[BATCH * HH * WW * NCC];
__device__ __align__(16) fp16 g_whx[9 * 2 * NCC * NCC];   // [tap][term][ci][co]
__device__ float g_bh[NCC];
__device__ __align__(16) float g_win[3 * 9 * NCC];
__device__ float g_bin[NCC];
__device__ __align__(16) float g_wout[NCC * 9 * 3];
__device__ float g_bout[3];

// ---------------- helpers ----------------
__device__ __forceinline__ float selu_f(float x) {
    const float sc = 1.0507009873554805f;
    const float scal = 1.7580993408473766f;
    return x > 0.f ? sc * x : scal * (expf(x) - 1.f);
}
__device__ __forceinline__ uint32_t smem_u32(const void* p) {
    uint32_t a;
    asm("{ .reg .u64 t; cvta.to.shared.u64 t, %1; cvt.u32.u64 %0, t; }" : "=r"(a) : "l"(p));
    return a;
}
__device__ __forceinline__ void cpa16(uint32_t dst, const void* src, bool pred) {
    int sz = pred ? 16 : 0;
    asm volatile("cp.async.cg.shared.global [%0], [%1], 16, %2;" :: "r"(dst), "l"(src), "r"(sz) : "memory");
}
#define CP_COMMIT() asm volatile("cp.async.commit_group;" ::: "memory")

// wait until at most n cp.async groups remain in flight (groups retire in order)
__device__ __forceinline__ void cp_wait_n(int n) {
    switch (n) {
        case 0: asm volatile("cp.async.wait_group 0;" ::: "memory"); break;
        case 1: asm volatile("cp.async.wait_group 1;" ::: "memory"); break;
        case 2: asm volatile("cp.async.wait_group 2;" ::: "memory"); break;
        case 3: asm volatile("cp.async.wait_group 3;" ::: "memory"); break;
        case 4: asm volatile("cp.async.wait_group 4;" ::: "memory"); break;
        case 5: asm volatile("cp.async.wait_group 5;" ::: "memory"); break;
        case 6: asm volatile("cp.async.wait_group 6;" ::: "memory"); break;
        case 7: asm volatile("cp.async.wait_group 7;" ::: "memory"); break;
        default: asm volatile("cp.async.wait_group 8;" ::: "memory"); break;
    }
}

__device__ __forceinline__ void ldsm_x4(uint32_t (&r)[4], uint32_t addr) {
    asm volatile("ldmatrix.sync.aligned.m8n8.x4.shared.b16 {%0,%1,%2,%3}, [%4];"
                 : "=r"(r[0]), "=r"(r[1]), "=r"(r[2]), "=r"(r[3]) : "r"(addr));
}
__device__ __forceinline__ void ldsm_x4t(uint32_t (&r)[4], uint32_t addr) {
    asm volatile("ldmatrix.sync.aligned.m8n8.x4.trans.shared.b16 {%0,%1,%2,%3}, [%4];"
                 : "=r"(r[0]), "=r"(r[1]), "=r"(r[2]), "=r"(r[3]) : "r"(addr));
}
__device__ __forceinline__ void mma16816(float (&d)[4], const uint32_t (&a)[4], uint32_t b0, uint32_t b1) {
    asm volatile("mma.sync.aligned.m16n8k16.row.col.f32.f16.f16.f32 "
                 "{%0,%1,%2,%3}, {%4,%5,%6,%7}, {%8,%9}, {%0,%1,%2,%3};"
                 : "+f"(d[0]), "+f"(d[1]), "+f"(d[2]), "+f"(d[3])
                 : "r"(a[0]), "r"(a[1]), "r"(a[2]), "r"(a[3]), "r"(b0), "r"(b1));
}

// smem: bias | A tiles [term(2)][inrow(4)] x 66px x 64ci | W all 9 taps resident
static constexpr int A_TILE = 66 * 128;                   // 8448 bytes per tile
static constexpr int SMEM_A = 1024;
static constexpr int SMEM_W = SMEM_A + 8 * A_TILE;        // 68608
static constexpr int WTAP = 2 * NCC * NCC * 2;            // 16384 bytes per tap
static constexpr int SMEM_TOT = SMEM_W + 9 * WTAP;        // 216064 (~211KB, 1 CTA/SM)

// ---------------- prep: fold BN, split weights to fp16 hi/lo ----------------
__global__ void prep_kernel(
    const float* __restrict__ w_in, const float* __restrict__ b_in,
    const float* __restrict__ g_in, const float* __restrict__ be_in,
    const float* __restrict__ m_in, const float* __restrict__ v_in,
    const float* __restrict__ w_h,  const float* __restrict__ b_h,
    const float* __restrict__ g_h,  const float* __restrict__ be_h,
    const float* __restrict__ m_h,  const float* __restrict__ v_h,
    const float* __restrict__ w_out, const float* __restrict__ b_out,
    const float* __restrict__ g_out, const float* __restrict__ be_out,
    const float* __restrict__ m_out, const float* __restrict__ v_out)
{
    int idx = blockIdx.x * blockDim.x + threadIdx.x;
    if (idx < 9 * 2 * NCC * NCC) {        // [tap][term][ci][co]
        int co = idx & 63;
        int ci = (idx >> 6) & 63;
        int term = (idx >> 12) & 1;
        int tap = idx >> 13;
        float s = g_h[co] * rsqrtf(v_h[co] + EPSV);
        float wf = w_h[(co * NCC + ci) * 9 + tap] * s;
        fp16 hi = __float2half_rn(wf);
        g_whx[idx] = (term == 0) ? hi : __float2half_rn(wf - __half2float(hi));
    }
    if (idx < 3 * 9 * NCC) {
        int co = idx & 63;
        int rest = idx >> 6;
        int tap = rest % 9;
        int ci = rest / 9;
        float s = g_in[co] * rsqrtf(v_in[co] + EPSV);
        g_win[idx] = w_in[(co * 3 + ci) * 9 + tap] * s;
    }
    if (idx < NCC * 9 * 3) {
        int co = idx % 3;
        int rest = idx / 3;
        int tap = rest % 9;
        int ci = rest / 9;
        float s = g_out[co] * rsqrtf(v_out[co] + EPSV);
        g_wout[idx] = w_out[(co * NCC + ci) * 9 + tap] * s;
    }
    if (idx < NCC) {
        g_bh[idx]  = (b_h[idx]  - m_h[idx])  * (g_h[idx]  * rsqrtf(v_h[idx]  + EPSV)) + be_h[idx];
        g_bin[idx] = (b_in[idx] - m_in[idx]) * (g_in[idx] * rsqrtf(v_in[idx] + EPSV)) + be_in[idx];
    }
    if (idx < 3) {
        g_bout[idx] = (b_out[idx] - m_out[idx]) * (g_out[idx] * rsqrtf(v_out[idx] + EPSV)) + be_out[idx];
    }
}

// ---------------- input conv 3->64 + BN + SELU, NCHW -> NHWC fp16 hi/lo ----------------
__global__ __launch_bounds__(128) void in_conv_kernel(const float* __restrict__ X,
                                                      fp16* __restrict__ oh, fp16* __restrict__ ol)
{
    __shared__ __align__(16) float s_w[3 * 9 * NCC];
    __shared__ __align__(16) float s_b[NCC];
    int tid = threadIdx.x;
    for (int i = tid; i < 3 * 9 * NCC; i += 128) s_w[i] = g_win[i];
    if (tid < NCC) s_b[tid] = g_bin[tid];
    __syncthreads();

    int p = blockIdx.x * 128 + tid;
    int b = p >> 16;
    int y = (p >> 8) & 255;
    int x = p & 255;
    const float* Xb = X + (size_t)b * 3 * HH * WW;

    float4 acc[16];
    #pragma unroll
    for (int q = 0; q < 16; q++) acc[q] = ((const float4*)s_b)[q];

    #pragma unroll
    for (int ci = 0; ci < 3; ci++) {
        #pragma unroll
        for (int dy = 0; dy < 3; dy++) {
            int gy = y + dy - 1;
            #pragma unroll
            for (int dx = 0; dx < 3; dx++) {
                int gx = x + dx - 1;
                float v = 0.f;
                if (gy >= 0 && gy < HH && gx >= 0 && gx < WW)
                    v = Xb[ci * HH * WW + gy * WW + gx];
                const float4* w4 = (const float4*)(s_w + (ci * 9 + dy * 3 + dx) * NCC);
                #pragma unroll
                for (int q = 0; q < 16; q++) {
                    float4 w = w4[q];
                    acc[q].x += v * w.x; acc[q].y += v * w.y;
                    acc[q].z += v * w.z; acc[q].w += v * w.w;
                }
            }
        }
    }
    fp16 hv[64], lv[64];
    #pragma unroll
    for (int q = 0; q < 16; q++) {
        float vv[4] = { acc[q].x, acc[q].y, acc[q].z, acc[q].w };
        #pragma unroll
        for (int j = 0; j < 4; j++) {
            float v = selu_f(vv[j]);
            fp16 h = __float2half_rn(v);
            hv[q * 4 + j] = h;
            lv[q * 4 + j] = __float2half_rn(v - __half2float(h));
        }
    }
    #pragma unroll
    for (int t = 0; t < 8; t++) {
        *(uint4*)(oh + (size_t)p * NCC + t * 8) = *(uint4*)(hv + t * 8);
        *(uint4*)(ol + (size_t)p * NCC + t * 8) = *(uint4*)(lv + t * 8);
    }
}

// ---------------- hidden conv 64->64 via mma.sync HMMA (3-term fp16 split) ----------------
// CTA: 256 thr = 8 warps, 1 CTA/SM; 2 output rows x 64 px strip; 64 co.
// ALL 9 taps' weights staged once (ordered cp.async groups); mainloop tap t
// does incremental wait_group(8-t) + 1 barrier, then pure LDSM+MMA.
__global__ __launch_bounds__(256, 1) void hidden_mma(const fp16* __restrict__ ah, const fp16* __restrict__ al,
                                                     fp16* __restrict__ oh, fp16* __restrict__ ol)
{
    extern __shared__ char smem[];
    float* s_bias = (float*)smem;
    uint32_t sAu = smem_u32(smem + SMEM_A);
    uint32_t sWu = smem_u32(smem + SMEM_W);
    int tid = threadIdx.x;
    int x0 = blockIdx.x * 64;
    int y0 = blockIdx.y * 2;
    int b  = blockIdx.z;

    if (tid < 64) s_bias[tid] = g_bh[tid];

    // --- group 0: A halo tiles + W tap 0 ---
    for (int j = tid; j < 8 * 66 * 8; j += 256) {
        int g = j & 7;
        int p = (j >> 3) % 66;
        int t3 = (j >> 3) / 66;             // term*4 + ri
        int ri = t3 & 3;
        int gx = x0 - 1 + p, gy = y0 - 1 + ri;
        bool v = (gx >= 0 && gx < WW && gy >= 0 && gy < HH);
        int gxc = v ? gx : 0;
        int gyc = (gy >= 0 && gy < HH) ? gy : 0;
        const fp16* base = (t3 >= 4) ? al : ah;
        const fp16* src = base + ((size_t)((b * HH + gyc) * WW) + gxc) * NCC + g * 8;
        uint32_t dst = sAu + t3 * A_TILE + p * 128 + ((g ^ (p & 7)) << 4);
        cpa16(dst, src, v);
    }
    {
        const char* src = (const char*)g_whx;
        for (int j = tid; j < 1024; j += 256) {
            int g = j & 7, ci = (j >> 3) & 63, term = j >> 9;
            uint32_t dst = sWu + term * 8192 + ci * 128 + ((g ^ (ci & 7)) << 4);
            cpa16(dst, src + term * 8192 + ci * 128 + g * 16, true);
        }
    }
    CP_COMMIT();
    // --- groups 1..8: W taps 1..8 ---
    #pragma unroll
    for (int t = 1; t < 9; ++t) {
        const char* src = (const char*)g_whx + t * WTAP;
        uint32_t dstb = sWu + t * WTAP;
        for (int j = tid; j < 1024; j += 256) {
            int g = j & 7, ci = (j >> 3) & 63, term = j >> 9;
            uint32_t dst = dstb + term * 8192 + ci * 128 + ((g ^ (ci & 7)) << 4);
            cpa16(dst, src + term * 8192 + ci * 128 + g * 16, true);
        }
        CP_COMMIT();
    }

    float acc[2][4][4];
    #pragma unroll
    for (int mt = 0; mt < 2; mt++)
        #pragma unroll
        for (int n0 = 0; n0 < 4; n0++)
            #pragma unroll
            for (int k = 0; k < 4; k++) acc[mt][n0][k] = 0.f;

    int lane = tid & 31;
    int w = tid >> 5;
    int r = w >> 2;                 // output row within CTA (0/1)
    int mp = ((w >> 1) & 1) * 32;   // warp's 32-px base
    int nh = w & 1;                 // co half (0/1)
    int mat = lane >> 3, rr = lane & 7;
    int mrow = ((mat & 1) << 3) + rr;   // A m_local within m16 tile
    int kh = mat >> 1;                  // A k-half
    int l16 = lane & 15;                // W ci row within k16
    int csel = lane >> 4;               // W co-column select (x4.trans)

    #pragma unroll
    for (int tap = 0; tap < 9; ++tap) {
        cp_wait_n(8 - tap);             // groups retire in order: tap's W (and A) ready
        __syncthreads();
        int dy = tap / 3, dx = tap % 3;
        int trow = r + dy;              // input-row tile index 0..3

        #pragma unroll
        for (int kc = 0; kc < 4; ++kc) {
            uint32_t a_hi[2][4], a_lo[2][4];
            #pragma unroll
            for (int mt = 0; mt < 2; mt++) {
                int s = mp + mt * 16 + mrow + dx;    // strip px 0..65
                int g = kc * 2 + kh;
                uint32_t arow = (uint32_t)(trow * A_TILE + s * 128 + ((g ^ (s & 7)) << 4));
                ldsm_x4(a_hi[mt], sAu + arow);
                ldsm_x4(a_lo[mt], sAu + 4 * A_TILE + arow);
            }
            int ci = kc * 16 + l16;
            uint32_t wrow = sWu + tap * WTAP + ci * 128;
            uint32_t sw = (ci & 7) << 4;
            #pragma unroll
            for (int p2 = 0; p2 < 2; ++p2) {
                int n0g = nh * 4 + p2 * 2 + csel;    // this lane-group's co column
                uint32_t bh4[4], bl4[4];
                uint32_t waddr = wrow + ((n0g << 4) ^ sw);
                ldsm_x4t(bh4, waddr);
                ldsm_x4t(bl4, waddr + 8192);
                int c0 = p2 * 2;
                mma16816(acc[0][c0],     a_hi[0], bh4[0], bh4[1]);
                mma16816(acc[1][c0],     a_hi[1], bh4[0], bh4[1]);
                mma16816(acc[0][c0 + 1], a_hi[0], bh4[2], bh4[3]);
                mma16816(acc[1][c0 + 1], a_hi[1], bh4[2], bh4[3]);
                mma16816(acc[0][c0],     a_lo[0], bh4[0], bh4[1]);
                mma16816(acc[1][c0],     a_lo[1], bh4[0], bh4[1]);
                mma16816(acc[0][c0 + 1], a_lo[0], bh4[2], bh4[3]);
                mma16816(acc[1][c0 + 1], a_lo[1], bh4[2], bh4[3]);
                mma16816(acc[0][c0],     a_hi[0], bl4[0], bl4[1]);
                mma16816(acc[1][c0],     a_hi[1], bl4[0], bl4[1]);
                mma16816(acc[0][c0 + 1], a_hi[0], bl4[2], bl4[3]);
                mma16816(acc[1][c0 + 1], a_hi[1], bl4[2], bl4[3]);
            }
        }
    }

    // --- epilogue: bias + SELU + fp16 hi/lo split, store NHWC ---
    int q = lane >> 2;
    int cp2 = (lane & 3) << 1;
    int gy = y0 + r;
    #pragma unroll
    for (int mt = 0; mt < 2; ++mt) {
        #pragma unroll
        for (int n0 = 0; n0 < 4; ++n0) {
            int cb = nh * 32 + n0 * 8 + cp2;
            float b0 = s_bias[cb];
            float b1 = s_bias[cb + 1];
            #pragma unroll
            for (int hr = 0; hr < 2; ++hr) {
                int px = mp + mt * 16 + q + hr * 8;
                float v0 = acc[mt][n0][hr * 2 + 0] + b0;
                float v1 = acc[mt][n0][hr * 2 + 1] + b1;
                v0 = selu_f(v0);
                v1 = selu_f(v1);
                fp16 h0 = __float2half_rn(v0);
                fp16 h1 = __float2half_rn(v1);
                fp16 lo0 = __float2half_rn(v0 - __half2float(h0));
                fp16 lo1 = __float2half_rn(v1 - __half2float(h1));
                size_t off = ((size_t)((b * HH + gy) * WW) + (x0 + px)) * NCC + cb;
                *(__half2*)(oh + off) = __halves2half2(h0, h1);
                *(__half2*)(ol + off) = __halves2half2(lo0, lo1);
            }
        }
    }
}

// ---------------- output conv 64->3 + BN + SELU + bayer residual ----------------
__global__ __launch_bounds__(128) void out_conv_kernel(const fp16* __restrict__ ah,
                                                       const fp16* __restrict__ al,
                                                       const float* __restrict__ X,
                                                       float* __restrict__ out)
{
    __shared__ float s_w[NCC * 9 * 3];
    __shared__ float s_b[4];
    int tid = threadIdx.x;
    for (int i = tid; i < NCC * 9 * 3; i += 128) s_w[i] = g_wout[i];
    if (tid < 3) s_b[tid] = g_bout[tid];
    __syncthreads();

    int p = blockIdx.x * 128 + tid;
    int b = p >> 16;
    int y = (p >> 8) & 255;
    int x = p & 255;

    float acc0 = s_b[0], acc1 = s_b[1], acc2 = s_b[2];
    #pragma unroll
    for (int dy = 0; dy < 3; dy++) {
        int gy = y + dy - 1;
        #pragma unroll
        for (int dx = 0; dx < 3; dx++) {
            int gx = x + dx - 1;
            if (gy < 0 || gy >= HH || gx < 0 || gx >= WW) continue;
            int tap = dy * 3 + dx;
            size_t base = ((size_t)b * HH * WW + (size_t)gy * WW + gx) * NCC;
            #pragma unroll
            for (int t = 0; t < 8; t++) {
                uint4 hraw = *(const uint4*)(ah + base + t * 8);
                uint4 lraw = *(const uint4*)(al + base + t * 8);
                const fp16* hp = (const fp16*)&hraw;
                const fp16* lp = (const fp16*)&lraw;
                #pragma unroll
                for (int j = 0; j < 8; j++) {
                    int ci = t * 8 + j;
                    float v = __half2float(hp[j]) + __half2float(lp[j]);
                    const float* w = s_w + (ci * 9 + tap) * 3;
                    acc0 += v * w[0]; acc1 += v * w[1]; acc2 += v * w[2];
                }
            }
        }
    }
    float sel[3] = { selu_f(acc0), selu_f(acc1), selu_f(acc2) };

    #pragma unroll
    for (int c = 0; c < 3; c++) {
        const float* Xc = X + ((size_t)b * 3 + c) * HH * WW;
        float xv = Xc[y * WW + x];
        float l = (x > 0)       ? Xc[y * WW + x - 1] : 0.f;
        float rr = (x < WW - 1) ? Xc[y * WW + x + 1] : 0.f;
        float t = (y > 0)       ? Xc[(y - 1) * WW + x] : 0.f;
        float bt = (y < HH - 1) ? Xc[(y + 1) * WW + x] : 0.f;
        float nb_sum = l + rr + t + bt;
        float nb_cnt = (l > 0.f) + (rr > 0.f) + (t > 0.f) + (bt > 0.f);
        float mean = nb_cnt > 0.f ? nb_sum / nb_cnt : 0.f;
        float res = (xv == 0.f) ? mean : xv;
        out[((size_t)b * 3 + c) * HH * WW + (size_t)y * WW + x] = sel[c] + res;
    }
}

// ---------------- launch ----------------
extern "C" void kernel_launch(void* const* d_in, const int* in_sizes, int n_in,
                              void* d_out, int out_size)
{
    const float* X     = (const float*)d_in[0];
    const float* w_in  = (const float*)d_in[1];
    const float* b_in  = (const float*)d_in[2];
    const float* gi    = (const float*)d_in[3];
    const float* bei   = (const float*)d_in[4];
    const float* mi    = (const float*)d_in[5];
    const float* vi    = (const float*)d_in[6];
    const float* w_h   = (const float*)d_in[7];
    const float* b_h   = (const float*)d_in[8];
    const float* gh    = (const float*)d_in[9];
    const float* beh   = (const float*)d_in[10];
    const float* mh    = (const float*)d_in[11];
    const float* vh    = (const float*)d_in[12];
    const float* w_out = (const float*)d_in[13];
    const float* b_out = (const float*)d_in[14];
    const float* go    = (const float*)d_in[15];
    const float* beo   = (const float*)d_in[16];
    const float* mo    = (const float*)d_in[17];
    const float* vo    = (const float*)d_in[18];
    float* out = (float*)d_out;

    fp16 *h0, *l0, *h1, *l1;
    cudaGetSymbolAddress((void**)&h0, g_h0);
    cudaGetSymbolAddress((void**)&l0, g_l0);
    cudaGetSymbolAddress((void**)&h1, g_h1);
    cudaGetSymbolAddress((void**)&l1, g_l1);

    cudaFuncSetAttribute(hidden_mma, cudaFuncAttributeMaxDynamicSharedMemorySize, SMEM_TOT);

    prep_kernel<<<(9 * 2 * NCC * NCC + 255) / 256, 256>>>(
        w_in, b_in, gi, bei, mi, vi,
        w_h, b_h, gh, beh, mh, vh,
        w_out, b_out, go, beo, mo, vo);

    const int NPIX = BATCH * HH * WW;
    in_conv_kernel<<<NPIX / 128, 128>>>(X, h0, l0);

    dim3 hgrid(WW / 64, HH / 2, BATCH);
    for (int lyr = 0; lyr < NHID; lyr++) {
        const fp16* sh = (lyr & 1) ? h1 : h0;
        const fp16* sl = (lyr & 1) ? l1 : l0;
        fp16* dh = (lyr & 1) ? h0 : h1;
        fp16* dl = (lyr & 1) ? l0 : l1;
        hidden_mma<<<hgrid, 256, SMEM_TOT>>>(sh, sl, dh, dl);
    }
    // NHID even -> final activations in (h0, l0)
    out_conv_kernel<<<NPIX / 128, 128>>>(h0, l0, X, out);
}

// round 15
// speedup vs baseline: 1.1864x; 1.1864x over previous
#include <cuda_runtime.h>
#include <cuda_fp16.h>
#include <cstdint>

#define BATCH 4
#define HH 256
#define WW 256
#define NCC 64
#define NHID 18
#define EPSV 1e-5f

typedef __half fp16;

// ---------------- device scratch ----------------
__device__ __align__(16) fp16 g_h0[BATCH * HH * WW * NCC];
__device__ __align__(16) fp16 g_l0[BATCH * HH * WW * NCC];
__device__ __align__(16) fp16 g_h1[BATCH * HH * WW * NCC];
__device__ __align__(16) fp16 g_l1[BATCH * HH * WW * NCC];
__device__ __align__(16) fp16 g_whx[9 * 2 * NCC * NCC];   // [tap][term][ci][co]
__device__ float g_bh[NCC];
__device__ __align__(16) float g_win[3 * 9 * NCC];
__device__ float g_bin[NCC];
__device__ __align__(16) float g_wout[NCC * 9 * 3];
__device__ float g_bout[3];

// ---------------- helpers ----------------
__device__ __forceinline__ float selu_f(float x) {
    const float sc = 1.0507009873554805f;
    const float scal = 1.7580993408473766f;
    return x > 0.f ? sc * x : scal * (expf(x) - 1.f);
}
__device__ __forceinline__ uint32_t smem_u32(const void* p) {
    uint32_t a;
    asm("{ .reg .u64 t; cvta.to.shared.u64 t, %1; cvt.u32.u64 %0, t; }" : "=r"(a) : "l"(p));
    return a;
}
__device__ __forceinline__ void cpa16(uint32_t dst, const void* src, bool pred) {
    int sz = pred ? 16 : 0;
    asm volatile("cp.async.cg.shared.global [%0], [%1], 16, %2;" :: "r"(dst), "l"(src), "r"(sz) : "memory");
}
#define CP_COMMIT() asm volatile("cp.async.commit_group;" ::: "memory")
#define CP_WAIT0()  asm volatile("cp.async.wait_group 0;" ::: "memory")

__device__ __forceinline__ void ldsm_x4(uint32_t (&r)[4], uint32_t addr) {
    asm volatile("ldmatrix.sync.aligned.m8n8.x4.shared.b16 {%0,%1,%2,%3}, [%4];"
                 : "=r"(r[0]), "=r"(r[1]), "=r"(r[2]), "=r"(r[3]) : "r"(addr));
}
__device__ __forceinline__ void ldsm_x4t(uint32_t (&r)[4], uint32_t addr) {
    asm volatile("ldmatrix.sync.aligned.m8n8.x4.trans.shared.b16 {%0,%1,%2,%3}, [%4];"
                 : "=r"(r[0]), "=r"(r[1]), "=r"(r[2]), "=r"(r[3]) : "r"(addr));
}
__device__ __forceinline__ void mma16816(float (&d)[4], const uint32_t (&a)[4], uint32_t b0, uint32_t b1) {
    asm volatile("mma.sync.aligned.m16n8k16.row.col.f32.f16.f16.f32 "
                 "{%0,%1,%2,%3}, {%4,%5,%6,%7}, {%8,%9}, {%0,%1,%2,%3};"
                 : "+f"(d[0]), "+f"(d[1]), "+f"(d[2]), "+f"(d[3])
                 : "r"(a[0]), "r"(a[1]), "r"(a[2]), "r"(a[3]), "r"(b0), "r"(b1));
}

// smem layout: bias | A tiles [term(2)][inrow(4)] x 66px x 64ci | W double-buffer
static constexpr int A_TILE = 66 * 128;                   // 8448 bytes per tile
static constexpr int SMEM_A = 1024;
static constexpr int SMEM_WB = SMEM_A + 8 * A_TILE;       // 68608
static constexpr int WSTAGE = 2 * NCC * NCC * 2;          // 16384 bytes per tap
static constexpr int SMEM_TOT = SMEM_WB + 2 * WSTAGE;     // 101376 (2 CTA/SM)

// ---------------- prep: fold BN, split weights to fp16 hi/lo ----------------
__global__ void prep_kernel(
    const float* __restrict__ w_in, const float* __restrict__ b_in,
    const float* __restrict__ g_in, const float* __restrict__ be_in,
    const float* __restrict__ m_in, const float* __restrict__ v_in,
    const float* __restrict__ w_h,  const float* __restrict__ b_h,
    const float* __restrict__ g_h,  const float* __restrict__ be_h,
    const float* __restrict__ m_h,  const float* __restrict__ v_h,
    const float* __restrict__ w_out, const float* __restrict__ b_out,
    const float* __restrict__ g_out, const float* __restrict__ be_out,
    const float* __restrict__ m_out, const float* __restrict__ v_out)
{
    int idx = blockIdx.x * blockDim.x + threadIdx.x;
    if (idx < 9 * 2 * NCC * NCC) {        // [tap][term][ci][co]
        int co = idx & 63;
        int ci = (idx >> 6) & 63;
        int term = (idx >> 12) & 1;
        int tap = idx >> 13;
        float s = g_h[co] * rsqrtf(v_h[co] + EPSV);
        float wf = w_h[(co * NCC + ci) * 9 + tap] * s;
        fp16 hi = __float2half_rn(wf);
        g_whx[idx] = (term == 0) ? hi : __float2half_rn(wf - __half2float(hi));
    }
    if (idx < 3 * 9 * NCC) {
        int co = idx & 63;
        int rest = idx >> 6;
        int tap = rest % 9;
        int ci = rest / 9;
        float s = g_in[co] * rsqrtf(v_in[co] + EPSV);
        g_win[idx] = w_in[(co * 3 + ci) * 9 + tap] * s;
    }
    if (idx < NCC * 9 * 3) {
        int co = idx % 3;
        int rest = idx / 3;
        int tap = rest % 9;
        int ci = rest / 9;
        float s = g_out[co] * rsqrtf(v_out[co] + EPSV);
        g_wout[idx] = w_out[(co * NCC + ci) * 9 + tap] * s;
    }
    if (idx < NCC) {
        g_bh[idx]  = (b_h[idx]  - m_h[idx])  * (g_h[idx]  * rsqrtf(v_h[idx]  + EPSV)) + be_h[idx];
        g_bin[idx] = (b_in[idx] - m_in[idx]) * (g_in[idx] * rsqrtf(v_in[idx] + EPSV)) + be_in[idx];
    }
    if (idx < 3) {
        g_bout[idx] = (b_out[idx] - m_out[idx]) * (g_out[idx] * rsqrtf(v_out[idx] + EPSV)) + be_out[idx];
    }
}

// ---------------- input conv 3->64 + BN + SELU, NCHW -> NHWC fp16 hi/lo ----------------
__global__ __launch_bounds__(128) void in_conv_kernel(const float* __restrict__ X,
                                                      fp16* __restrict__ oh, fp16* __restrict__ ol)
{
    __shared__ __align__(16) float s_w[3 * 9 * NCC];
    __shared__ __align__(16) float s_b[NCC];
    int tid = threadIdx.x;
    for (int i = tid; i < 3 * 9 * NCC; i += 128) s_w[i] = g_win[i];
    if (tid < NCC) s_b[tid] = g_bin[tid];
    __syncthreads();

    int p = blockIdx.x * 128 + tid;
    int b = p >> 16;
    int y = (p >> 8) & 255;
    int x = p & 255;
    const float* Xb = X + (size_t)b * 3 * HH * WW;

    float4 acc[16];
    #pragma unroll
    for (int q = 0; q < 16; q++) acc[q] = ((const float4*)s_b)[q];

    #pragma unroll
    for (int ci = 0; ci < 3; ci++) {
        #pragma unroll
        for (int dy = 0; dy < 3; dy++) {
            int gy = y + dy - 1;
            #pragma unroll
            for (int dx = 0; dx < 3; dx++) {
                int gx = x + dx - 1;
                float v = 0.f;
                if (gy >= 0 && gy < HH && gx >= 0 && gx < WW)
                    v = Xb[ci * HH * WW + gy * WW + gx];
                const float4* w4 = (const float4*)(s_w + (ci * 9 + dy * 3 + dx) * NCC);
                #pragma unroll
                for (int q = 0; q < 16; q++) {
                    float4 w = w4[q];
                    acc[q].x += v * w.x; acc[q].y += v * w.y;
                    acc[q].z += v * w.z; acc[q].w += v * w.w;
                }
            }
        }
    }
    fp16 hv[64], lv[64];
    #pragma unroll
    for (int q = 0; q < 16; q++) {
        float vv[4] = { acc[q].x, acc[q].y, acc[q].z, acc[q].w };
        #pragma unroll
        for (int j = 0; j < 4; j++) {
            float v = selu_f(vv[j]);
            fp16 h = __float2half_rn(v);
            hv[q * 4 + j] = h;
            lv[q * 4 + j] = __float2half_rn(v - __half2float(h));
        }
    }
    #pragma unroll
    for (int t = 0; t < 8; t++) {
        *(uint4*)(oh + (size_t)p * NCC + t * 8) = *(uint4*)(hv + t * 8);
        *(uint4*)(ol + (size_t)p * NCC + t * 8) = *(uint4*)(lv + t * 8);
    }
}

// ---------------- hidden conv 64->64 via mma.sync HMMA (3-term fp16 split) ----------------
// CTA: 256 thr = 8 warps, 2 CTAs/SM; 2 output rows x 64 px strip; 64 co.
// Warp = (r: row) x (st: 32-px strip) x (nh: co half); per-warp tile M=32, N=32.
// W double-buffered per tap; ONE barrier per tap (top sync orders prior-tap reads
// before next prefetch overwrite). Address math hoisted out of the kc loop.
__global__ __launch_bounds__(256, 2) void hidden_mma(const fp16* __restrict__ ah, const fp16* __restrict__ al,
                                                     fp16* __restrict__ oh, fp16* __restrict__ ol)
{
    extern __shared__ char smem[];
    float* s_bias = (float*)smem;
    uint32_t sAu = smem_u32(smem + SMEM_A);
    uint32_t sWu = smem_u32(smem + SMEM_WB);
    int tid = threadIdx.x;
    int x0 = blockIdx.x * 64;
    int y0 = blockIdx.y * 2;
    int b  = blockIdx.z;

    if (tid < 64) s_bias[tid] = g_bh[tid];

    // --- A halo tile loads: 8 tiles (term x 4 input rows) x 66 px x 8 groups of 16B ---
    for (int j = tid; j < 8 * 66 * 8; j += 256) {
        int g = j & 7;
        int p = (j >> 3) % 66;
        int t3 = (j >> 3) / 66;             // term*4 + ri
        int ri = t3 & 3;
        int gx = x0 - 1 + p, gy = y0 - 1 + ri;
        bool v = (gx >= 0 && gx < WW && gy >= 0 && gy < HH);
        int gxc = v ? gx : 0;
        int gyc = (gy >= 0 && gy < HH) ? gy : 0;
        const fp16* base = (t3 >= 4) ? al : ah;
        const fp16* src = base + ((size_t)((b * HH + gyc) * WW) + gxc) * NCC + g * 8;
        uint32_t dst = sAu + t3 * A_TILE + p * 128 + ((g ^ (p & 7)) << 4);
        cpa16(dst, src, v);
    }
    // --- stage W tap 0 into buf 0 ---
    {
        const char* src = (const char*)g_whx;
        for (int j = tid; j < 1024; j += 256) {
            int g = j & 7, ci = (j >> 3) & 63, term = j >> 9;
            uint32_t dst = sWu + term * 8192 + ci * 128 + ((g ^ (ci & 7)) << 4);
            cpa16(dst, src + term * 8192 + ci * 128 + g * 16, true);
        }
    }
    CP_COMMIT();

    float acc[2][4][4];
    #pragma unroll
    for (int mt = 0; mt < 2; mt++)
        #pragma unroll
        for (int n0 = 0; n0 < 4; n0++)
            #pragma unroll
            for (int k = 0; k < 4; k++) acc[mt][n0][k] = 0.f;

    int lane = tid & 31;
    int w = tid >> 5;
    int r = w >> 2;                 // output row within CTA (0/1)
    int mp = ((w >> 1) & 1) * 32;   // warp's 32-px base
    int nh = w & 1;                 // co half (0/1)
    int mat = lane >> 3, rr = lane & 7;
    int mrow = ((mat & 1) << 3) + rr;   // A m_local within m16 tile
    int kh = mat >> 1;                  // A k-half
    int l16 = lane & 15;                // W ci row within k16
    int csel = lane >> 4;               // W co-column select (x4.trans)

    // hoisted W-address invariants: (kc*16 + l16) & 7 == l16 & 7
    uint32_t w_sw = (uint32_t)((l16 & 7) << 4);
    uint32_t w_rowoff = (uint32_t)(l16 * 128);
    uint32_t w_coloff[2];
    #pragma unroll
    for (int p2 = 0; p2 < 2; ++p2) {
        int n0g = nh * 4 + p2 * 2 + csel;
        w_coloff[p2] = (uint32_t)((n0g << 4) ^ w_sw);
    }

    int wbuf = 0;
    #pragma unroll
    for (int tap = 0; tap < 9; ++tap) {
        CP_WAIT0();
        __syncthreads();                 // single barrier per tap (see header comment)
        if (tap < 8) {
            const char* src = (const char*)g_whx + (tap + 1) * WSTAGE;
            uint32_t dstb = sWu + (wbuf ^ 1) * WSTAGE;
            for (int j = tid; j < 1024; j += 256) {
                int g = j & 7, ci = (j >> 3) & 63, term = j >> 9;
                uint32_t dst = dstb + term * 8192 + ci * 128 + ((g ^ (ci & 7)) << 4);
                cpa16(dst, src + term * 8192 + ci * 128 + g * 16, true);
            }
            CP_COMMIT();
        }
        int dy = tap / 3, dx = tap % 3;
        int trow = r + dy;                  // input-row tile index 0..3

        // hoisted A-address invariants for this tap
        int s0 = mp + mrow + dx;            // mt=0 strip px
        int s1 = s0 + 16;                   // mt=1 strip px
        uint32_t aBase0 = sAu + (uint32_t)(trow * A_TILE + s0 * 128);
        uint32_t aBase1 = aBase0 + 16 * 128;
        uint32_t c0x = (uint32_t)(s0 & 7);
        uint32_t c1x = (uint32_t)(s1 & 7);
        uint32_t wBase = sWu + (uint32_t)(wbuf * WSTAGE) + w_rowoff;

        #pragma unroll
        for (int kc = 0; kc < 4; ++kc) {
            int g = kc * 2 + kh;
            uint32_t off0 = (uint32_t)((g ^ c0x) << 4);
            uint32_t off1 = (uint32_t)((g ^ c1x) << 4);
            uint32_t a_hi[2][4], a_lo[2][4];
            ldsm_x4(a_hi[0], aBase0 + off0);
            ldsm_x4(a_lo[0], aBase0 + off0 + 4 * A_TILE);
            ldsm_x4(a_hi[1], aBase1 + off1);
            ldsm_x4(a_lo[1], aBase1 + off1 + 4 * A_TILE);

            uint32_t wrow = wBase + (uint32_t)(kc * 2048);
            #pragma unroll
            for (int p2 = 0; p2 < 2; ++p2) {
                uint32_t bh4[4], bl4[4];
                uint32_t waddr = wrow + w_coloff[p2];
                ldsm_x4t(bh4, waddr);
                ldsm_x4t(bl4, waddr + 8192);
                int c0 = p2 * 2;
                mma16816(acc[0][c0],     a_hi[0], bh4[0], bh4[1]);
                mma16816(acc[1][c0],     a_hi[1], bh4[0], bh4[1]);
                mma16816(acc[0][c0 + 1], a_hi[0], bh4[2], bh4[3]);
                mma16816(acc[1][c0 + 1], a_hi[1], bh4[2], bh4[3]);
                mma16816(acc[0][c0],     a_lo[0], bh4[0], bh4[1]);
                mma16816(acc[1][c0],     a_lo[1], bh4[0], bh4[1]);
                mma16816(acc[0][c0 + 1], a_lo[0], bh4[2], bh4[3]);
                mma16816(acc[1][c0 + 1], a_lo[1], bh4[2], bh4[3]);
                mma16816(acc[0][c0],     a_hi[0], bl4[0], bl4[1]);
                mma16816(acc[1][c0],     a_hi[1], bl4[0], bl4[1]);
                mma16816(acc[0][c0 + 1], a_hi[0], bl4[2], bl4[3]);
                mma16816(acc[1][c0 + 1], a_hi[1], bl4[2], bl4[3]);
            }
        }
        wbuf ^= 1;
    }

    // --- epilogue: bias + SELU + fp16 hi/lo split, store NHWC ---
    int q = lane >> 2;
    int cp2 = (lane & 3) << 1;
    int gy = y0 + r;
    #pragma unroll
    for (int mt = 0; mt < 2; ++mt) {
        #pragma unroll
        for (int n0 = 0; n0 < 4; ++n0) {
            int cb = nh * 32 + n0 * 8 + cp2;
            float b0 = s_bias[cb];
            float b1 = s_bias[cb + 1];
            #pragma unroll
            for (int hr = 0; hr < 2; ++hr) {
                int px = mp + mt * 16 + q + hr * 8;
                float v0 = acc[mt][n0][hr * 2 + 0] + b0;
                float v1 = acc[mt][n0][hr * 2 + 1] + b1;
                v0 = selu_f(v0);
                v1 = selu_f(v1);
                fp16 h0 = __float2half_rn(v0);
                fp16 h1 = __float2half_rn(v1);
                fp16 lo0 = __float2half_rn(v0 - __half2float(h0));
                fp16 lo1 = __float2half_rn(v1 - __half2float(h1));
                size_t off = ((size_t)((b * HH + gy) * WW) + (x0 + px)) * NCC + cb;
                *(__half2*)(oh + off) = __halves2half2(h0, h1);
                *(__half2*)(ol + off) = __halves2half2(lo0, lo1);
            }
        }
    }
}

// ---------------- output conv 64->3 + BN + SELU + bayer residual ----------------
__global__ __launch_bounds__(128) void out_conv_kernel(const fp16* __restrict__ ah,
                                                       const fp16* __restrict__ al,
                                                       const float* __restrict__ X,
                                                       float* __restrict__ out)
{
    __shared__ float s_w[NCC * 9 * 3];
    __shared__ float s_b[4];
    int tid = threadIdx.x;
    for (int i = tid; i < NCC * 9 * 3; i += 128) s_w[i] = g_wout[i];
    if (tid < 3) s_b[tid] = g_bout[tid];
    __syncthreads();

    int p = blockIdx.x * 128 + tid;
    int b = p >> 16;
    int y = (p >> 8) & 255;
    int x = p & 255;

    float acc0 = s_b[0], acc1 = s_b[1], acc2 = s_b[2];
    #pragma unroll
    for (int dy = 0; dy < 3; dy++) {
        int gy = y + dy - 1;
        #pragma unroll
        for (int dx = 0; dx < 3; dx++) {
            int gx = x + dx - 1;
            if (gy < 0 || gy >= HH || gx < 0 || gx >= WW) continue;
            int tap = dy * 3 + dx;
            size_t base = ((size_t)b * HH * WW + (size_t)gy * WW + gx) * NCC;
            #pragma unroll
            for (int t = 0; t < 8; t++) {
                uint4 hraw = *(const uint4*)(ah + base + t * 8);
                uint4 lraw = *(const uint4*)(al + base + t * 8);
                const fp16* hp = (const fp16*)&hraw;
                const fp16* lp = (const fp16*)&lraw;
                #pragma unroll
                for (int j = 0; j < 8; j++) {
                    int ci = t * 8 + j;
                    float v = __half2float(hp[j]) + __half2float(lp[j]);
                    const float* w = s_w + (ci * 9 + tap) * 3;
                    acc0 += v * w[0]; acc1 += v * w[1]; acc2 += v * w[2];
                }
            }
        }
    }
    float sel[3] = { selu_f(acc0), selu_f(acc1), selu_f(acc2) };

    #pragma unroll
    for (int c = 0; c < 3; c++) {
        const float* Xc = X + ((size_t)b * 3 + c) * HH * WW;
        float xv = Xc[y * WW + x];
        float l = (x > 0)       ? Xc[y * WW + x - 1] : 0.f;
        float rr = (x < WW - 1) ? Xc[y * WW + x + 1] : 0.f;
        float t = (y > 0)       ? Xc[(y - 1) * WW + x] : 0.f;
        float bt = (y < HH - 1) ? Xc[(y + 1) * WW + x] : 0.f;
        float nb_sum = l + rr + t + bt;
        float nb_cnt = (l > 0.f) + (rr > 0.f) + (t > 0.f) + (bt > 0.f);
        float mean = nb_cnt > 0.f ? nb_sum / nb_cnt : 0.f;
        float res = (xv == 0.f) ? mean : xv;
        out[((size_t)b * 3 + c) * HH * WW + (size_t)y * WW + x] = sel[c] + res;
    }
}

// ---------------- launch ----------------
extern "C" void kernel_launch(void* const* d_in, const int* in_sizes, int n_in,
                              void* d_out, int out_size)
{
    const float* X     = (const float*)d_in[0];
    const float* w_in  = (const float*)d_in[1];
    const float* b_in  = (const float*)d_in[2];
    const float* gi    = (const float*)d_in[3];
    const float* bei   = (const float*)d_in[4];
    const float* mi    = (const float*)d_in[5];
    const float* vi    = (const float*)d_in[6];
    const float* w_h   = (const float*)d_in[7];
    const float* b_h   = (const float*)d_in[8];
    const float* gh    = (const float*)d_in[9];
    const float* beh   = (const float*)d_in[10];
    const float* mh    = (const float*)d_in[11];
    const float* vh    = (const float*)d_in[12];
    const float* w_out = (const float*)d_in[13];
    const float* b_out = (const float*)d_in[14];
    const float* go    = (const float*)d_in[15];
    const float* beo   = (const float*)d_in[16];
    const float* mo    = (const float*)d_in[17];
    const float* vo    = (const float*)d_in[18];
    float* out = (float*)d_out;

    fp16 *h0, *l0, *h1, *l1;
    cudaGetSymbolAddress((void**)&h0, g_h0);
    cudaGetSymbolAddress((void**)&l0, g_l0);
    cudaGetSymbolAddress((void**)&h1, g_h1);
    cudaGetSymbolAddress((void**)&l1, g_l1);

    cudaFuncSetAttribute(hidden_mma, cudaFuncAttributeMaxDynamicSharedMemorySize, SMEM_TOT);

    prep_kernel<<<(9 * 2 * NCC * NCC + 255) / 256, 256>>>(
        w_in, b_in, gi, bei, mi, vi,
        w_h, b_h, gh, beh, mh, vh,
        w_out, b_out, go, beo, mo, vo);

    const int NPIX = BATCH * HH * WW;
    in_conv_kernel<<<NPIX / 128, 128>>>(X, h0, l0);

    dim3 hgrid(WW / 64, HH / 2, BATCH);
    for (int lyr = 0; lyr < NHID; lyr++) {
        const fp16* sh = (lyr & 1) ? h1 : h0;
        const fp16* sl = (lyr & 1) ? l1 : l0;
        fp16* dh = (lyr & 1) ? h0 : h1;
        fp16* dl = (lyr & 1) ? l0 : l1;
        hidden_mma<<<hgrid, 256, SMEM_TOT>>>(sh, sl, dh, dl);
    }
    // NHID even -> final activations in (h0, l0)
    out_conv_kernel<<<NPIX / 128, 128>>>(h0, l0, X, out);
}